// round 5
// baseline (speedup 1.0000x reference)
#include <cuda_runtime.h>
#include <stdint.h>

// Problem constants (fixed by the reference problem definition)
#define FEAT_DIM 128
#define BATCH    4
#define NY       512
#define NX       512
#define NYNX     (NY * NX)
#define NPIX     (BATCH * NYNX)      // 1,048,576

#define XT   64        // x-tile per block
#define NTH  256       // 8 warps; cap 4 blocks/SM -> 32 warps/SM (sweet spot)

// 4 MB scratch: winner map. INVARIANT: all-zero on entry to kernel_launch.
//  - zero at module load (device globals are zero-initialized)
//  - k_argmax writes (voxel_index + 1) via atomicMax (last-write-wins == max idx)
//  - k_gather restores every nonzero entry it consumed back to 0
// => no init kernel, identical work every call (graph-replay safe).
__device__ int g_map[NPIX];

// ---------------------------------------------------------------------------
// Kernel 1: winner per pixel.  coors: [N,4] int32 (b, z, y, x)
// 2 voxels per thread (2x int4 loads per iteration).
// ---------------------------------------------------------------------------
__global__ void k_argmax_map(const int* __restrict__ coors, int n) {
    int i = (blockIdx.x * blockDim.x + threadIdx.x) * 2;
    if (i < n) {
        int4 c = reinterpret_cast<const int4*>(coors)[i];
        atomicMax(&g_map[c.x * NYNX + c.z * NX + c.w], i + 1);
    }
    if (i + 1 < n) {
        int4 c = reinterpret_cast<const int4*>(coors)[i + 1];
        atomicMax(&g_map[c.x * NYNX + c.z * NX + c.w], i + 2);
    }
}

// ---------------------------------------------------------------------------
// Kernel 2: gather + transpose, 128-bit vectorized via quad XOR swizzle.
// Tile: 64 pixels x 128 channels, physical float index
//   P(x, c) = x*128 + ((c>>2 ^ (x&31)) << 2) + (c&3)
// Fill : warp=pixel, lane=quad  -> LDG.128 + STS.128, conflict-free.
// Drain: lane=x, fixed quad     -> LDS.128 conflict-free + 4x coalesced STG.32.
// 32 warps/SM deliberately (higher occupancy measured SLOWER: L1tex-queue
// contention + write-stream fragmentation; see R1 vs R3/R4).
// ---------------------------------------------------------------------------
__global__ __launch_bounds__(NTH, 4)
void k_gather(const float* __restrict__ feat, float* __restrict__ out) {
    __shared__ float tile[XT * FEAT_DIM];   // 32 KB, swizzled

    int blk = blockIdx.x;              // 0 .. BATCH*NY*(NX/XT)-1
    int xt  = blk & (NX / XT - 1);     // 0..7
    int y   = (blk >> 3) & (NY - 1);   // 0..511
    int b   = blk >> 12;               // 0..3
    int x0  = xt * XT;

    int t = threadIdx.x, warp = t >> 5, lane = t & 31;
    int mapbase = b * NYNX + y * NX + x0;

    // ---- Fill: 8 warps x 8 pixels each ----
    #pragma unroll
    for (int m = 0; m < XT / 8; m++) {
        int xl  = m * 8 + warp;
        int idx = mapbase + xl;
        int v   = g_map[idx];                       // uniform broadcast load
        float4 val;
        if (v > 0) {
            val = reinterpret_cast<const float4*>(
                      feat + (size_t)(v - 1) * FEAT_DIM)[lane];   // LDG.128
            if (lane == 0) g_map[idx] = 0;          // restore invariant
        } else {
            val = make_float4(0.f, 0.f, 0.f, 0.f);
        }
        int sw = (lane ^ (xl & 31)) << 2;           // quad swizzle
        *reinterpret_cast<float4*>(&tile[xl * FEAT_DIM + sw]) = val;  // STS.128
    }
    __syncthreads();

    // ---- Drain: 64 items (quad q 0..31, x-half) / 8 warps = 8 each ----
    size_t pixbase = (size_t)b * FEAT_DIM * NYNX + (size_t)y * NX + x0;
    #pragma unroll
    for (int m = 0; m < 8; m++) {
        int item = m * 8 + warp;                    // 0..63
        int q    = item >> 1;                       // channel quad 0..31
        int x    = ((item & 1) << 5) + lane;        // 0..63
        float4 val = *reinterpret_cast<const float4*>(
            &tile[x * FEAT_DIM + ((q ^ (x & 31)) << 2)]);         // LDS.128
        size_t o = pixbase + (size_t)(4 * q) * NYNX + x;
        out[o]            = val.x;                  // 4 x 128B coalesced STG
        out[o +     NYNX] = val.y;
        out[o + 2 * NYNX] = val.z;
        out[o + 3 * NYNX] = val.w;
    }
}

// ---------------------------------------------------------------------------
extern "C" void kernel_launch(void* const* d_in, const int* in_sizes, int n_in,
                              void* d_out, int out_size) {
    const float* feat  = (const float*)d_in[0];
    const int*   coors = (const int*)d_in[1];
    float*       out   = (float*)d_out;

    int n = in_sizes[0] / FEAT_DIM;   // number of voxels

    // 1) winner per pixel (map is all-zero by invariant)
    k_argmax_map<<<(n / 2 + 255) / 256, 256>>>(coors, n);
    // 2) gather + transpose full output (and restore map to zero)
    k_gather<<<BATCH * NY * (NX / XT), NTH>>>(feat, out);
}

// round 6
// speedup vs baseline: 1.1812x; 1.1812x over previous
#include <cuda_runtime.h>
#include <stdint.h>

// Problem constants (fixed by the reference problem definition)
#define FEAT_DIM 128
#define BATCH    4
#define NY       512
#define NX       512
#define NYNX     (NY * NX)
#define NPIX     (BATCH * NYNX)      // 1,048,576

#define XT   64        // x-tile per block (2 pipelined halves of 32)
#define NTH  256       // 8 warps; 6 blocks/SM (smem-limited) = 48 warps + stagger

// 4 MB scratch: winner map. INVARIANT: all-zero on entry to kernel_launch.
//  - zero at module load (device globals are zero-initialized)
//  - k_argmax writes (voxel_index + 1) via atomicMax (last-write-wins == max idx)
//  - k_gather restores every nonzero entry it consumed back to 0
__device__ int g_map[NPIX];

// ---------------------------------------------------------------------------
// Kernel 1: winner per pixel.  coors: [N,4] int32 (b, z, y, x)
// ---------------------------------------------------------------------------
__global__ void k_argmax_map(const int* __restrict__ coors, int n) {
    int i = (blockIdx.x * blockDim.x + threadIdx.x) * 2;
    if (i < n) {
        int4 c = reinterpret_cast<const int4*>(coors)[i];
        atomicMax(&g_map[c.x * NYNX + c.z * NX + c.w], i + 1);
    }
    if (i + 1 < n) {
        int4 c = reinterpret_cast<const int4*>(coors)[i + 1];
        atomicMax(&g_map[c.x * NYNX + c.z * NX + c.w], i + 2);
    }
}

// ---------------------------------------------------------------------------
// Kernel 2: gather + transpose, 128-bit vectorized, quad XOR swizzle,
// SOFTWARE-PIPELINED across two 32-pixel half-tiles:
//     vidx ; sync ; fill(A) ; sync ; fill(B) || drain(A) ; sync ; drain(B)
// so reads (LDG) and writes (STG) are in flight simultaneously per block.
// Swizzle: P(xl, c) = xl*128 + ((c>>2 ^ xl) << 2) + (c&3), xl = x & 31.
//   Fill : warp=pixel, lane=quad  -> LDG.128 + STS.128, conflict-free.
//   Drain: lane=x-in-half, per-quad -> LDS.128 conflict-free + 4 coalesced STG.
// ---------------------------------------------------------------------------
__device__ __forceinline__ void fill_half(const float* __restrict__ feat,
                                          float* __restrict__ buf,
                                          const int* __restrict__ vidx,
                                          int h, int warp, int lane) {
    #pragma unroll
    for (int m = 0; m < 4; m++) {
        int px = h * 32 + m * 8 + warp;          // global pixel in tile
        int xl = px & 31;                        // row in half-buffer
        int v  = vidx[px];
        float4 val;
        if (v >= 0) {
            val = __ldcs(reinterpret_cast<const float4*>(
                             feat + (size_t)v * FEAT_DIM) + lane);   // LDG.128
        } else {
            val = make_float4(0.f, 0.f, 0.f, 0.f);
        }
        *reinterpret_cast<float4*>(
            &buf[xl * FEAT_DIM + ((lane ^ xl) << 2)]) = val;         // STS.128
    }
}

__device__ __forceinline__ void drain_half(float* __restrict__ out,
                                           const float* __restrict__ buf,
                                           size_t pixbase, int h,
                                           int warp, int lane) {
    #pragma unroll
    for (int m = 0; m < 4; m++) {
        int q = m * 8 + warp;                    // channel quad 0..31
        float4 val = *reinterpret_cast<const float4*>(
            &buf[lane * FEAT_DIM + ((q ^ lane) << 2)]);              // LDS.128
        size_t o = pixbase + (size_t)(4 * q) * NYNX + h * 32 + lane;
        __stcs(out + o,            val.x);       // 4 x 128B coalesced STG
        __stcs(out + o +     NYNX, val.y);
        __stcs(out + o + 2 * NYNX, val.z);
        __stcs(out + o + 3 * NYNX, val.w);
    }
}

__global__ __launch_bounds__(NTH, 6)
void k_gather(const float* __restrict__ feat, float* __restrict__ out) {
    __shared__ float bufA[32 * FEAT_DIM];   // 16 KB
    __shared__ float bufB[32 * FEAT_DIM];   // 16 KB
    __shared__ int   vidx[XT];

    int blk = blockIdx.x;              // 0 .. BATCH*NY*(NX/XT)-1
    int xt  = blk & (NX / XT - 1);     // 0..7
    int y   = (blk >> 3) & (NY - 1);   // 0..511
    int b   = blk >> 12;               // 0..3
    int x0  = xt * XT;

    int t = threadIdx.x, warp = t >> 5, lane = t & 31;

    if (t < XT) {
        int idx = b * NYNX + y * NX + x0 + t;
        int v = g_map[idx];
        vidx[t] = v - 1;               // -1 if empty
        if (v) g_map[idx] = 0;         // restore all-zero invariant
    }
    __syncthreads();

    size_t pixbase = (size_t)b * FEAT_DIM * NYNX + (size_t)y * NX + x0;

    fill_half(feat, bufA, vidx, 0, warp, lane);
    __syncthreads();
    fill_half(feat, bufB, vidx, 1, warp, lane);      // reads in flight...
    drain_half(out, bufA, pixbase, 0, warp, lane);   // ...while writes drain
    __syncthreads();
    drain_half(out, bufB, pixbase, 1, warp, lane);
}

// ---------------------------------------------------------------------------
extern "C" void kernel_launch(void* const* d_in, const int* in_sizes, int n_in,
                              void* d_out, int out_size) {
    const float* feat  = (const float*)d_in[0];
    const int*   coors = (const int*)d_in[1];
    float*       out   = (float*)d_out;

    int n = in_sizes[0] / FEAT_DIM;   // number of voxels

    // 1) winner per pixel (map is all-zero by invariant)
    k_argmax_map<<<(n / 2 + 255) / 256, 256>>>(coors, n);
    // 2) gather + transpose full output (and restore map to zero)
    k_gather<<<BATCH * NY * (NX / XT), NTH>>>(feat, out);
}

// round 7
// speedup vs baseline: 1.2867x; 1.0893x over previous
#include <cuda_runtime.h>
#include <stdint.h>

// Problem constants (fixed by the reference problem definition)
#define FEAT_DIM 128
#define BATCH    4
#define NY       512
#define NX       512
#define NYNX     (NY * NX)
#define NPIX     (BATCH * NYNX)      // 1,048,576

#define XT   64        // x-tile per block (2 pipelined halves of 32)
#define NTH  512       // 16 warps; 4 blocks/SM (smem) = 64 warps

// 4 MB scratch: winner map. INVARIANT: all-zero on entry to kernel_launch.
//  - zero at module load (device globals are zero-initialized)
//  - k_argmax writes (voxel_index + 1) via atomicMax (last-write-wins == max idx)
//  - k_gather restores every nonzero entry it consumed back to 0
__device__ int g_map[NPIX];

// ---------------------------------------------------------------------------
// cp.async helpers: 16B global->shared, src_size=0 => zero-fill (empty pixels)
// ---------------------------------------------------------------------------
__device__ __forceinline__ uint32_t smem_u32(const void* p) {
    return (uint32_t)__cvta_generic_to_shared(p);
}
__device__ __forceinline__ void cp_async16(uint32_t dst, const void* src, int src_size) {
    asm volatile("cp.async.cg.shared.global [%0], [%1], 16, %2;\n"
                 :: "r"(dst), "l"(src), "r"(src_size));
}
__device__ __forceinline__ void cp_commit() {
    asm volatile("cp.async.commit_group;\n" ::: "memory");
}
template <int N>
__device__ __forceinline__ void cp_wait() {
    asm volatile("cp.async.wait_group %0;\n" :: "n"(N) : "memory");
}

// ---------------------------------------------------------------------------
// Kernel 1: winner per pixel.  coors: [N,4] int32 (b, z, y, x)
// ---------------------------------------------------------------------------
__global__ void k_argmax_map(const int* __restrict__ coors, int n) {
    int i = (blockIdx.x * blockDim.x + threadIdx.x) * 2;
    if (i < n) {
        int4 c = reinterpret_cast<const int4*>(coors)[i];
        atomicMax(&g_map[c.x * NYNX + c.z * NX + c.w], i + 1);
    }
    if (i + 1 < n) {
        int4 c = reinterpret_cast<const int4*>(coors)[i + 1];
        atomicMax(&g_map[c.x * NYNX + c.z * NX + c.w], i + 2);
    }
}

// ---------------------------------------------------------------------------
// Kernel 2: gather + transpose. cp.async fills (no reg residency, no RAW
// scoreboard), quad-XOR-swizzled smem, pipelined so half-B reads stream
// from DRAM while half-A writes drain:
//   vidx ; fillA ; commit ; fillB ; commit ; wait<1> ; sync ;
//   drainA (B in flight) ; wait<0> ; sync ; drainB
// Swizzle: P(xl, c) = xl*128 + ((c>>2 ^ xl) << 2) + (c&3), xl = x & 31.
//   Fill : warp=pixel, lane=quad -> cp.async 16B, conflict-free smem dst.
//   Drain: lane=x-in-half, quad per item -> LDS.128 + 4x coalesced STG.32.
// ---------------------------------------------------------------------------
__global__ __launch_bounds__(NTH, 4)
void k_gather(const float* __restrict__ feat, float* __restrict__ out) {
    __shared__ float buf[2][32 * FEAT_DIM];   // 2 x 16 KB
    __shared__ int   vidx[XT];

    int blk = blockIdx.x;              // 0 .. BATCH*NY*(NX/XT)-1
    int xt  = blk & (NX / XT - 1);     // 0..7
    int y   = (blk >> 3) & (NY - 1);   // 0..511
    int b   = blk >> 12;               // 0..3
    int x0  = xt * XT;

    int t = threadIdx.x, warp = t >> 5, lane = t & 31;

    if (t < XT) {
        int idx = b * NYNX + y * NX + x0 + t;
        int v = g_map[idx];
        vidx[t] = v - 1;               // -1 if empty
        if (v) g_map[idx] = 0;         // restore all-zero invariant
    }
    __syncthreads();

    // ---- Fill both halves via cp.async (2 pixels per warp per half) ----
    #pragma unroll
    for (int h = 0; h < 2; h++) {
        #pragma unroll
        for (int m = 0; m < 2; m++) {
            int xl = warp * 2 + m;                 // 0..31 within half
            int v  = vidx[h * 32 + xl];
            uint32_t dst = smem_u32(&buf[h][xl * FEAT_DIM + ((lane ^ xl) << 2)]);
            const float* src = feat + (size_t)(v < 0 ? 0 : v) * FEAT_DIM + lane * 4;
            cp_async16(dst, src, v < 0 ? 0 : 16);  // zfill empties
        }
        cp_commit();
    }

    size_t pixbase = (size_t)b * FEAT_DIM * NYNX + (size_t)y * NX + x0;

    // ---- Drain half A while half B's reads are still in flight ----
    cp_wait<1>();
    __syncthreads();
    #pragma unroll
    for (int m = 0; m < 2; m++) {
        int q = warp * 2 + m;                      // channel quad 0..31
        float4 val = *reinterpret_cast<const float4*>(
            &buf[0][lane * FEAT_DIM + ((q ^ lane) << 2)]);   // LDS.128
        size_t o = pixbase + (size_t)(4 * q) * NYNX + lane;
        out[o]            = val.x;                 // 4 x 128B coalesced STG
        out[o +     NYNX] = val.y;
        out[o + 2 * NYNX] = val.z;
        out[o + 3 * NYNX] = val.w;
    }

    // ---- Drain half B ----
    cp_wait<0>();
    __syncthreads();
    #pragma unroll
    for (int m = 0; m < 2; m++) {
        int q = warp * 2 + m;
        float4 val = *reinterpret_cast<const float4*>(
            &buf[1][lane * FEAT_DIM + ((q ^ lane) << 2)]);
        size_t o = pixbase + (size_t)(4 * q) * NYNX + 32 + lane;
        out[o]            = val.x;
        out[o +     NYNX] = val.y;
        out[o + 2 * NYNX] = val.z;
        out[o + 3 * NYNX] = val.w;
    }
}

// ---------------------------------------------------------------------------
extern "C" void kernel_launch(void* const* d_in, const int* in_sizes, int n_in,
                              void* d_out, int out_size) {
    const float* feat  = (const float*)d_in[0];
    const int*   coors = (const int*)d_in[1];
    float*       out   = (float*)d_out;

    int n = in_sizes[0] / FEAT_DIM;   // number of voxels

    // 1) winner per pixel (map is all-zero by invariant)
    k_argmax_map<<<(n / 2 + 255) / 256, 256>>>(coors, n);
    // 2) gather + transpose full output (and restore map to zero)
    k_gather<<<BATCH * NY * (NX / XT), NTH>>>(feat, out);
}

// round 8
// speedup vs baseline: 1.4073x; 1.0937x over previous
#include <cuda_runtime.h>
#include <stdint.h>

// Problem constants (fixed by the reference problem definition)
#define FEAT_DIM 128
#define BATCH    4
#define NY       512
#define NX       512
#define NYNX     (NY * NX)
#define NPIX     (BATCH * NYNX)      // 1,048,576

#define XT    128      // x-tile per block (4 pipelined stages of 32)
#define NSTG  4        // pipeline stages
#define SPX   32       // pixels per stage
#define NTH   512      // 16 warps; 3 blocks/SM (smem 66KB) = 48 warps

// 4 MB scratch: winner map. INVARIANT: all-zero on entry to kernel_launch.
//  - zero at module load (device globals are zero-initialized)
//  - k_argmax writes (voxel_index + 1) via atomicMax (last-write-wins == max idx)
//  - k_gather restores every nonzero entry it consumed back to 0
__device__ int g_map[NPIX];

// ---------------------------------------------------------------------------
// cp.async helpers: 16B global->shared, src_size=0 => zero-fill (empty pixels)
// ---------------------------------------------------------------------------
__device__ __forceinline__ uint32_t smem_u32(const void* p) {
    return (uint32_t)__cvta_generic_to_shared(p);
}
__device__ __forceinline__ void cp_async16(uint32_t dst, const void* src, int src_size) {
    asm volatile("cp.async.cg.shared.global [%0], [%1], 16, %2;\n"
                 :: "r"(dst), "l"(src), "r"(src_size));
}
__device__ __forceinline__ void cp_commit() {
    asm volatile("cp.async.commit_group;\n" ::: "memory");
}
template <int N>
__device__ __forceinline__ void cp_wait() {
    asm volatile("cp.async.wait_group %0;\n" :: "n"(N) : "memory");
}

// ---------------------------------------------------------------------------
// Kernel 1: winner per pixel.  coors: [N,4] int32 (b, z, y, x)
// ---------------------------------------------------------------------------
__global__ void k_argmax_map(const int* __restrict__ coors, int n) {
    int i = (blockIdx.x * blockDim.x + threadIdx.x) * 2;
    if (i < n) {
        int4 c = reinterpret_cast<const int4*>(coors)[i];
        atomicMax(&g_map[c.x * NYNX + c.z * NX + c.w], i + 1);
    }
    if (i + 1 < n) {
        int4 c = reinterpret_cast<const int4*>(coors)[i + 1];
        atomicMax(&g_map[c.x * NYNX + c.z * NX + c.w], i + 2);
    }
}

// ---------------------------------------------------------------------------
// Kernel 2: gather + transpose. 4-stage cp.async pipeline over a 128-pixel
// x-tile (512B contiguous per (channel,y) output row -> better DRAM write
// locality than 256B @ XT=64). Schedule:
//   fill(0..3) each committed; then for s=0..3: wait<3-s>; sync; drain(s)
// so ~3 stages of reads are always streaming behind each drain phase.
// Swizzle: P(xl, c) = xl*128 + ((c>>2 ^ xl) << 2) + (c&3), xl = x % 32.
//   Fill : warp=pixel, lane=quad -> cp.async 16B, conflict-free smem dst.
//   Drain: lane=x-in-stage, quad per item -> LDS.128 + 4x coalesced STG.32.
// ---------------------------------------------------------------------------
__global__ __launch_bounds__(NTH, 3)
void k_gather(const float* __restrict__ feat, float* __restrict__ out) {
    __shared__ float buf[NSTG][SPX * FEAT_DIM];   // 4 x 16 KB
    __shared__ int   vidx[XT];

    int blk = blockIdx.x;              // 0 .. BATCH*NY*(NX/XT)-1
    int xt  = blk & (NX / XT - 1);     // 0..3
    int y   = (blk >> 2) & (NY - 1);   // 0..511
    int b   = blk >> 11;               // 0..3
    int x0  = xt * XT;

    int t = threadIdx.x, warp = t >> 5, lane = t & 31;

    if (t < XT) {
        int idx = b * NYNX + y * NX + x0 + t;
        int v = g_map[idx];
        vidx[t] = v - 1;               // -1 if empty
        if (v) g_map[idx] = 0;         // restore all-zero invariant
    }
    __syncthreads();

    // ---- Fill all 4 stages via cp.async (2 pixels per warp per stage) ----
    #pragma unroll
    for (int s = 0; s < NSTG; s++) {
        #pragma unroll
        for (int m = 0; m < 2; m++) {
            int xl = warp * 2 + m;                 // 0..31 within stage
            int v  = vidx[s * SPX + xl];
            uint32_t dst = smem_u32(&buf[s][xl * FEAT_DIM + ((lane ^ xl) << 2)]);
            const float* src = feat + (size_t)(v < 0 ? 0 : v) * FEAT_DIM + lane * 4;
            cp_async16(dst, src, v < 0 ? 0 : 16);  // zfill empties
        }
        cp_commit();
    }

    size_t pixbase = (size_t)b * FEAT_DIM * NYNX + (size_t)y * NX + x0;

    // ---- Drain stage s while stages s+1.. still stream from DRAM ----
    #pragma unroll
    for (int s = 0; s < NSTG; s++) {
        if (s == 0)      cp_wait<3>();
        else if (s == 1) cp_wait<2>();
        else if (s == 2) cp_wait<1>();
        else             cp_wait<0>();
        __syncthreads();
        #pragma unroll
        for (int m = 0; m < 2; m++) {
            int q = warp * 2 + m;                  // channel quad 0..31
            float4 val = *reinterpret_cast<const float4*>(
                &buf[s][lane * FEAT_DIM + ((q ^ lane) << 2)]);  // LDS.128
            size_t o = pixbase + (size_t)(4 * q) * NYNX + s * SPX + lane;
            out[o]            = val.x;             // 4 x 128B coalesced STG
            out[o +     NYNX] = val.y;
            out[o + 2 * NYNX] = val.z;
            out[o + 3 * NYNX] = val.w;
        }
    }
}

// ---------------------------------------------------------------------------
extern "C" void kernel_launch(void* const* d_in, const int* in_sizes, int n_in,
                              void* d_out, int out_size) {
    const float* feat  = (const float*)d_in[0];
    const int*   coors = (const int*)d_in[1];
    float*       out   = (float*)d_out;

    int n = in_sizes[0] / FEAT_DIM;   // number of voxels

    // 1) winner per pixel (map is all-zero by invariant)
    k_argmax_map<<<(n / 2 + 255) / 256, 256>>>(coors, n);
    // 2) gather + transpose full output (and restore map to zero)
    k_gather<<<BATCH * NY * (NX / XT), NTH>>>(feat, out);
}